// round 16
// baseline (speedup 1.0000x reference)
#include <cuda_runtime.h>
#include <cuda_fp16.h>
#include <math.h>
#include <stdint.h>

#define N_TOK 8192
#define DIM   1024
#define NEXP  8
#define DFF   4096
#define NPAIR (2 * N_TOK)
#define CAP   N_TOK                      // max rows per expert (top-2 distinct)

// ======================= device scratch (statics only) =======================
__device__ __half g_X[(size_t)N_TOK * DIM];              // x fp16
__device__ __half g_W1t[(size_t)NEXP * DFF * DIM];       // [e][n][k] fp16
__device__ __half g_W2t[(size_t)NEXP * DIM * DFF];       // [e][d][f] fp16
__device__ __half g_H[(size_t)NEXP * CAP * DFF];         // silu(h) fp16 (slabbed)
__device__ __half g_O[(size_t)NEXP * CAP * DIM];         // weighted outs fp16
__device__ int   g_cursor[NEXP];
__device__ int   g_done1[NEXP];                          // GEMM1 tiles complete
__device__ int   g_done2[NEXP];                          // conv-W2 tiles complete
__device__ int   g_pair_token[NEXP * CAP];
__device__ float g_pair_weight[NEXP * CAP];
__device__ int   g_tok2pair[NPAIR];

// ======================= PTX helpers =======================
__device__ __forceinline__ uint32_t smem_u32(const void* p) {
    uint32_t a;
    asm("{ .reg .u64 t; cvta.to.shared.u64 t, %1; cvt.u32.u64 %0, t; }"
        : "=r"(a) : "l"(p));
    return a;
}
__device__ __forceinline__ void cp16(uint32_t dst, const void* src, bool valid) {
    int sz = valid ? 16 : 0;
    asm volatile("cp.async.cg.shared.global [%0], [%1], 16, %2;"
                 :: "r"(dst), "l"(src), "r"(sz));
}
#define CP_COMMIT() asm volatile("cp.async.commit_group;" ::: "memory")
#define CP_WAIT(n)  asm volatile("cp.async.wait_group %0;" :: "n"(n) : "memory")

__device__ __forceinline__ void ldsm_x4(uint32_t* r, uint32_t addr) {
    asm volatile("ldmatrix.sync.aligned.m8n8.x4.shared.b16 {%0,%1,%2,%3}, [%4];"
                 : "=r"(r[0]), "=r"(r[1]), "=r"(r[2]), "=r"(r[3]) : "r"(addr));
}
__device__ __forceinline__ void mma_fp16(float* c, const uint32_t* a,
                                         uint32_t b0, uint32_t b1) {
    asm volatile("mma.sync.aligned.m16n8k16.row.col.f32.f16.f16.f32 "
                 "{%0,%1,%2,%3},{%4,%5,%6,%7},{%8,%9},{%0,%1,%2,%3};"
                 : "+f"(c[0]), "+f"(c[1]), "+f"(c[2]), "+f"(c[3])
                 : "r"(a[0]), "r"(a[1]), "r"(a[2]), "r"(a[3]), "r"(b0), "r"(b1));
}

static __device__ __forceinline__ uint32_t swz(uint32_t off) {
    return off ^ ((off >> 3) & 0x70);
}

// =========== device helper: transpose-convert one 64x64 fp32 tile ==========
template <int NCOLS>
__device__ __forceinline__ void conv_tile(const float* __restrict__ We,
                                          __half* __restrict__ Te,
                                          float (*tile)[65],
                                          int n0, int k0, int K) {
    int tid = threadIdx.x;
    int tx = tid & 63, ty = tid >> 6;
#pragma unroll
    for (int j = 0; j < 16; j++) {
        int kr = j * 4 + ty;
        tile[tx][kr] = We[(size_t)(k0 + kr) * NCOLS + n0 + tx];
    }
    __syncthreads();
    int w = tid >> 5, lane = tid & 31;
#pragma unroll
    for (int i = 0; i < 8; i++) {
        int n = w * 8 + i;
        __half2 h = __floats2half2_rn(tile[n][lane * 2], tile[n][lane * 2 + 1]);
        *(__half2*)&Te[(size_t)(n0 + n) * K + k0 + lane * 2] = h;
    }
}

// ======== kernel 1: convert W1 (blocks [0,8192)) + router (blocks [8192,8448)) ========
__global__ __launch_bounds__(256) void k_conv1_router(const float* __restrict__ w1,
                                                      const float* __restrict__ x,
                                                      const float* __restrict__ gw) {
    __shared__ float tile[64][65];
    int bx = blockIdx.x;
    if (bx < 8192) {
        int e = bx >> 10, t = bx & 1023;
        int n0 = (t & 63) * 64, k0 = (t >> 6) * 64;
        conv_tile<DFF>(w1 + (size_t)e * DIM * DFF,
                       &g_W1t[(size_t)e * DFF * DIM], tile, n0, k0, DIM);
        return;
    }
    // ---- router: 4 tokens/warp, fused x->fp16, direct slab assignment ----
    int b = bx - 8192;
    int wid = threadIdx.x >> 5, lane = threadIdx.x & 31;
    int warp = b * 8 + wid;
    int t0 = warp * 4;
    const float* xb = x + (size_t)t0 * DIM;
    __half* xo = &g_X[(size_t)t0 * DIM];

    float acc[4][8];
#pragma unroll
    for (int t = 0; t < 4; t++)
#pragma unroll
        for (int e = 0; e < 8; e++) acc[t][e] = 0.f;

    for (int d = lane; d < DIM; d += 32) {
        float4 ga = *(const float4*)(gw + (size_t)d * NEXP);
        float4 gb = *(const float4*)(gw + (size_t)d * NEXP + 4);
#pragma unroll
        for (int t = 0; t < 4; t++) {
            float xv = xb[t * DIM + d];
            xo[t * DIM + d] = __float2half(xv);
            acc[t][0] += xv * ga.x; acc[t][1] += xv * ga.y;
            acc[t][2] += xv * ga.z; acc[t][3] += xv * ga.w;
            acc[t][4] += xv * gb.x; acc[t][5] += xv * gb.y;
            acc[t][6] += xv * gb.z; acc[t][7] += xv * gb.w;
        }
    }
#pragma unroll
    for (int t = 0; t < 4; t++)
#pragma unroll
        for (int e = 0; e < 8; e++)
#pragma unroll
            for (int s = 16; s > 0; s >>= 1)
                acc[t][e] += __shfl_xor_sync(0xFFFFFFFFu, acc[t][e], s);

    if (lane < 4) {
        int t = t0 + lane;
        float* a = acc[lane];
        int e0 = 0; float b0 = a[0];
#pragma unroll
        for (int e = 1; e < NEXP; e++) if (a[e] > b0) { b0 = a[e]; e0 = e; }
        int e1 = -1; float b1 = -INFINITY;
#pragma unroll
        for (int e = 0; e < NEXP; e++) if (e != e0 && a[e] > b1) { b1 = a[e]; e1 = e; }
        float w0 = 1.f / (1.f + expf(b1 - b0));
        int ee[2] = { e0, e1 };
        float ww[2] = { w0, 1.f - w0 };
#pragma unroll
        for (int s = 0; s < 2; s++) {
            int pos = atomicAdd(&g_cursor[ee[s]], 1);
            int idx = ee[s] * CAP + pos;
            g_pair_token[idx]  = t;
            g_pair_weight[idx] = ww[s];
            g_tok2pair[2 * t + s] = idx;
        }
    }
}

// ======================= mma.sync GEMM cores =======================
#define PLANE_B (128 * 128)             // 16384
#define STAGE_B (2 * PLANE_B)           // 32768
#define SMEM_BYTES (2 * STAGE_B)        // 65536 -> 2 CTAs/SM

// Shared GEMM body (converged structure).
// G1: H = silu(X_gathered @ W1t^T), K=1024 (NC=16)
// !G1: O(fp16) = w * (H @ W2t^T),   K=4096 (NC=64)
template <int NC, bool G1>
__device__ __forceinline__ void gemm_body(int e, int cnt, char* dynsmem) {
    const int row0 = blockIdx.y * 128;
    const int off  = e * CAP;
    const int n0   = blockIdx.x * 128;

    const uint32_t sb = smem_u32(dynsmem);
    const int tid  = threadIdx.x;
    const int lane = tid & 31;
    const int wid  = tid >> 5;
    const int wm   = wid & 1;
    const int wn   = wid >> 1;

    const int r    = tid >> 1;
    const int half = tid & 1;
    const int row  = row0 + r;
    const bool vA  = row < cnt;

    const char* srcA;
    const char* srcB;
    if (G1) {
        int tok = vA ? g_pair_token[off + row] : 0;
        srcA = (const char*)(&g_X[0] + (size_t)tok * DIM) + half * 64;
        srcB = (const char*)(&g_W1t[0] + ((size_t)e * DFF + n0 + r) * DIM) + half * 64;
    } else {
        size_t p = (size_t)(vA ? off + row : off);
        srcA = (const char*)(&g_H[0] + p * DFF) + half * 64;
        srcB = (const char*)(&g_W2t[0] + ((size_t)e * DIM + n0 + r) * DFF) + half * 64;
    }
    uint32_t dstO[4];
#pragma unroll
    for (int j = 0; j < 4; j++)
        dstO[j] = swz((uint32_t)(r * 128 + half * 64 + j * 16));

    const int mat  = lane >> 3;
    const int lrow = lane & 7;
    const uint32_t xmask = (uint32_t)(lrow << 4);
    const uint32_t aBase = (uint32_t)((wm * 64 + (mat & 1) * 8 + lrow) * 128 + (mat >> 1) * 16);
    const uint32_t bBase = (uint32_t)((wn * 32 + (mat >> 1) * 8 + lrow) * 128 + (mat & 1) * 16);

    float c[4][4][4];
#pragma unroll
    for (int i = 0; i < 4; i++)
#pragma unroll
        for (int j = 0; j < 4; j++)
#pragma unroll
            for (int q = 0; q < 4; q++) c[i][j][q] = 0.f;

    auto load_stage = [&](int cidx) {
        uint32_t st = sb + (uint32_t)(cidx & 1) * STAGE_B;
        size_t ko = (size_t)cidx * 128;
#pragma unroll
        for (int j = 0; j < 4; j++)
            cp16(st + dstO[j], srcA + ko + j * 16, vA);
#pragma unroll
        for (int j = 0; j < 4; j++)
            cp16(st + PLANE_B + dstO[j], srcB + ko + j * 16, true);
        CP_COMMIT();
    };

    load_stage(0);

    for (int cidx = 0; cidx < NC; cidx++) {
        CP_WAIT(0);
        __syncthreads();
        if (cidx + 1 < NC) load_stage(cidx + 1);

        uint32_t st = sb + (uint32_t)(cidx & 1) * STAGE_B;
#pragma unroll
        for (int ks = 0; ks < 4; ks++) {
            uint32_t kso = (uint32_t)(ks * 32);
            uint32_t a[4][4], b[2][4];
#pragma unroll
            for (int tm = 0; tm < 4; tm++)
                ldsm_x4(a[tm], st + ((aBase + (uint32_t)(tm * 16 * 128) + kso) ^ xmask));
#pragma unroll
            for (int tp = 0; tp < 2; tp++)
                ldsm_x4(b[tp], st + PLANE_B + ((bBase + (uint32_t)(tp * 16 * 128) + kso) ^ xmask));
#pragma unroll
            for (int tm = 0; tm < 4; tm++)
#pragma unroll
                for (int tp = 0; tp < 2; tp++) {
                    mma_fp16(c[tm][tp * 2 + 0], a[tm], b[tp][0], b[tp][1]);
                    mma_fp16(c[tm][tp * 2 + 1], a[tm], b[tp][2], b[tp][3]);
                }
        }
    }

    const int g   = lane >> 2;
    const int tig = lane & 3;
#pragma unroll
    for (int tm = 0; tm < 4; tm++) {
#pragma unroll
        for (int half_m = 0; half_m < 2; half_m++) {
            int rr = row0 + wm * 64 + tm * 16 + g + half_m * 8;
            if (rr >= cnt) continue;
            if (G1) {
                size_t hrow = (size_t)(off + rr) * DFF + n0 + wn * 32 + tig * 2;
#pragma unroll
                for (int tn = 0; tn < 4; tn++) {
                    float v0 = c[tm][tn][half_m * 2 + 0];
                    float v1 = c[tm][tn][half_m * 2 + 1];
                    v0 = v0 / (1.f + __expf(-v0));
                    v1 = v1 / (1.f + __expf(-v1));
                    *(__half2*)(&g_H[0] + hrow + tn * 8) = __floats2half2_rn(v0, v1);
                }
            } else {
                float wgt = g_pair_weight[off + rr];
                size_t orow = (size_t)(off + rr) * DIM + n0 + wn * 32 + tig * 2;
#pragma unroll
                for (int tn = 0; tn < 4; tn++) {
                    *(__half2*)(&g_O[0] + orow + tn * 8) =
                        __floats2half2_rn(wgt * c[tm][tn][half_m * 2 + 0],
                                          wgt * c[tm][tn][half_m * 2 + 1]);
                }
            }
        }
    }
}

// ======== kernel 2 (fused): GEMM1 [z<8] + conv W2 [z in 8,9] + GEMM2 [z in 10,18) ====
// Dispatch is bid-ordered (z slow-major): all producers precede consumers, so a
// spinning GEMM2 CTA always coexists with >=1 running producer CTA -> no deadlock.
__global__ __launch_bounds__(256, 2) void k_gemms(const float* __restrict__ w2) {
    extern __shared__ char dynsmem[];
    int z = blockIdx.z;

    if (z < NEXP) {
        // ---- GEMM1 tile ----
        int e = z;
        int cnt = g_cursor[e];
        if (blockIdx.y * 128 >= cnt) return;
        gemm_body<DIM / 64, true>(e, cnt, dynsmem);
        __threadfence();                       // release H stores
        __syncthreads();
        if (threadIdx.x == 0) atomicAdd(&g_done1[e], 1);
        return;
    }
    if (z < NEXP + 2) {
        // ---- convert W2 tile: idx in [0, 8192) ----
        int idx = (z - NEXP) * 4096 + blockIdx.y * 32 + blockIdx.x;
        if (idx >= 8192) return;
        int e = idx >> 10, t = idx & 1023;
        int n0 = (t & 15) * 64, k0 = (t >> 4) * 64;
        float (*tile)[65] = (float(*)[65])dynsmem;
        conv_tile<DIM>(w2 + (size_t)e * DFF * DIM,
                       &g_W2t[(size_t)e * DIM * DFF], tile, n0, k0, DFF);
        __threadfence();                       // release W2t stores
        __syncthreads();
        if (threadIdx.x == 0) atomicAdd(&g_done2[e], 1);
        return;
    }
    // ---- GEMM2 tile (waits on its expert's GEMM1 + conv-W2) ----
    int e = z - (NEXP + 2);
    if (blockIdx.x >= DIM / 128 || blockIdx.y >= CAP / 128) return;
    int cnt = g_cursor[e];
    if (blockIdx.y * 128 >= cnt) return;
    if (threadIdx.x == 0) {
        int t1 = (DFF / 128) * ((cnt + 127) >> 7);
        while (atomicAdd(&g_done1[e], 0) < t1)   __nanosleep(256);
        while (atomicAdd(&g_done2[e], 0) < 1024) __nanosleep(256);
    }
    __syncthreads();
    __threadfence();                            // acquire
    gemm_body<DFF / 64, false>(e, cnt, dynsmem);
}

// ======== kernel 3: combine (fp16 O -> fp32 y) + counter resets for next run ==
__global__ void k_combine(float* __restrict__ y) {
    if (blockIdx.x == 0 && threadIdx.x < NEXP) {
        g_cursor[threadIdx.x] = 0;
        g_done1[threadIdx.x] = 0;
        g_done2[threadIdx.x] = 0;
    }
    int i = blockIdx.x * blockDim.x + threadIdx.x;
    const int V = DIM / 4;
    if (i >= N_TOK * V) return;
    int tok = i / V;
    int c   = i - tok * V;
    int p0 = g_tok2pair[2 * tok];
    int p1 = g_tok2pair[2 * tok + 1];
    const __half2* o0 = (const __half2*)(&g_O[0] + (size_t)p0 * DIM) + c * 2;
    const __half2* o1 = (const __half2*)(&g_O[0] + (size_t)p1 * DIM) + c * 2;
    float2 a0 = __half22float2(o0[0]);
    float2 a1 = __half22float2(o0[1]);
    float2 b0 = __half22float2(o1[0]);
    float2 b1 = __half22float2(o1[1]);
    float4 r;
    r.x = a0.x + b0.x; r.y = a0.y + b0.y;
    r.z = a1.x + b1.x; r.w = a1.y + b1.y;
    ((float4*)y)[i] = r;
}

// ======================= launch =======================
extern "C" void kernel_launch(void* const* d_in, const int* in_sizes, int n_in,
                              void* d_out, int out_size) {
    const float* x  = (const float*)d_in[0];   // [N, D]
    const float* gw = (const float*)d_in[1];   // [D, E]
    const float* w1 = (const float*)d_in[2];   // [E, D, DFF]
    const float* w2 = (const float*)d_in[3];   // [E, DFF, D]
    float* y = (float*)d_out;

    cudaFuncSetAttribute((const void*)k_gemms,
                         cudaFuncAttributeMaxDynamicSharedMemorySize, SMEM_BYTES);

    // #1: convert W1 + router (direct slab assignment; counters zeroed by
    //     previous run's combine / zero-init statics on first run)
    k_conv1_router<<<8192 + 256, 256>>>(w1, x, gw);
    // #2: fused GEMM1 + conv W2 + GEMM2 with per-expert software dependencies
    k_gemms<<<dim3(DFF / 128, 128, NEXP + 2 + NEXP), 256, SMEM_BYTES>>>(w2);
    // #3: combine (+ counter resets for next graph replay)
    k_combine<<<(N_TOK * DIM / 4 + 255) / 256, 256>>>(y);
}

// round 17
// speedup vs baseline: 1.0513x; 1.0513x over previous
#include <cuda_runtime.h>
#include <cuda_fp16.h>
#include <math.h>
#include <stdint.h>

#define N_TOK 8192
#define DIM   1024
#define NEXP  8
#define DFF   4096
#define NPAIR (2 * N_TOK)
#define CAP   N_TOK                      // max rows per expert (top-2 distinct)

// ======================= device scratch (statics only) =======================
__device__ __half g_X[(size_t)N_TOK * DIM];              // x fp16
__device__ __half g_W1t[(size_t)NEXP * DFF * DIM];       // [e][n][k] fp16
__device__ __half g_W2t[(size_t)NEXP * DIM * DFF];       // [e][d][f] fp16
__device__ __half g_H[(size_t)NEXP * CAP * DFF];         // silu(h) fp16 (slabbed)
__device__ __half g_O[(size_t)NEXP * CAP * DIM];         // weighted outs fp16
__device__ int   g_cursor[NEXP];
__device__ int   g_pair_token[NEXP * CAP];
__device__ float g_pair_weight[NEXP * CAP];
__device__ int   g_tok2pair[NPAIR];

// ======================= PTX helpers =======================
__device__ __forceinline__ uint32_t smem_u32(const void* p) {
    uint32_t a;
    asm("{ .reg .u64 t; cvta.to.shared.u64 t, %1; cvt.u32.u64 %0, t; }"
        : "=r"(a) : "l"(p));
    return a;
}
__device__ __forceinline__ void cp16(uint32_t dst, const void* src, bool valid) {
    int sz = valid ? 16 : 0;
    asm volatile("cp.async.cg.shared.global [%0], [%1], 16, %2;"
                 :: "r"(dst), "l"(src), "r"(sz));
}
#define CP_COMMIT() asm volatile("cp.async.commit_group;" ::: "memory")
#define CP_WAIT(n)  asm volatile("cp.async.wait_group %0;" :: "n"(n) : "memory")

__device__ __forceinline__ void ldsm_x4(uint32_t* r, uint32_t addr) {
    asm volatile("ldmatrix.sync.aligned.m8n8.x4.shared.b16 {%0,%1,%2,%3}, [%4];"
                 : "=r"(r[0]), "=r"(r[1]), "=r"(r[2]), "=r"(r[3]) : "r"(addr));
}
__device__ __forceinline__ void mma_fp16(float* c, const uint32_t* a,
                                         uint32_t b0, uint32_t b1) {
    asm volatile("mma.sync.aligned.m16n8k16.row.col.f32.f16.f16.f32 "
                 "{%0,%1,%2,%3},{%4,%5,%6,%7},{%8,%9},{%0,%1,%2,%3};"
                 : "+f"(c[0]), "+f"(c[1]), "+f"(c[2]), "+f"(c[3])
                 : "r"(a[0]), "r"(a[1]), "r"(a[2]), "r"(a[3]), "r"(b0), "r"(b1));
}

static __device__ __forceinline__ uint32_t swz(uint32_t off) {
    return off ^ ((off >> 3) & 0x70);
}

// =========== device helper: transpose-convert one 64x64 fp32 tile ==========
// float4 loads: thread t loads 4 consecutive n-values per pass (512B/warp/instr).
template <int NCOLS>
__device__ __forceinline__ void conv_tile(const float* __restrict__ We,
                                          __half* __restrict__ Te,
                                          float (*tile)[65],
                                          int n0, int k0, int K) {
    int tid = threadIdx.x;
    int n4 = (tid & 15) * 4;          // n offset (float4 granule)
    int kb = tid >> 4;                // 0..15
#pragma unroll
    for (int j = 0; j < 4; j++) {
        int kr = j * 16 + kb;
        float4 v = *(const float4*)(We + (size_t)(k0 + kr) * NCOLS + n0 + n4);
        tile[n4 + 0][kr] = v.x;
        tile[n4 + 1][kr] = v.y;
        tile[n4 + 2][kr] = v.z;
        tile[n4 + 3][kr] = v.w;
    }
    __syncthreads();
    int w = tid >> 5, lane = tid & 31;
#pragma unroll
    for (int i = 0; i < 8; i++) {
        int n = w * 8 + i;
        __half2 h = __floats2half2_rn(tile[n][lane * 2], tile[n][lane * 2 + 1]);
        *(__half2*)&Te[(size_t)(n0 + n) * K + k0 + lane * 2] = h;
    }
}

// ======== kernel 1: convert W1 (blocks [0,8192)) + router (blocks [8192,8448)) ========
// Router assigns compacted slab positions directly (no separate assign pass).
__global__ __launch_bounds__(256) void k_conv1_router(const float* __restrict__ w1,
                                                      const float* __restrict__ x,
                                                      const float* __restrict__ gw) {
    __shared__ float tile[64][65];
    int bx = blockIdx.x;
    if (bx < 8192) {
        int e = bx >> 10, t = bx & 1023;
        int n0 = (t & 63) * 64, k0 = (t >> 6) * 64;
        conv_tile<DFF>(w1 + (size_t)e * DIM * DFF,
                       &g_W1t[(size_t)e * DFF * DIM], tile, n0, k0, DIM);
        return;
    }
    // ---- router: 4 tokens/warp, fused x->fp16, direct slab assignment ----
    int b = bx - 8192;
    int wid = threadIdx.x >> 5, lane = threadIdx.x & 31;
    int warp = b * 8 + wid;
    int t0 = warp * 4;
    const float* xb = x + (size_t)t0 * DIM;
    __half* xo = &g_X[(size_t)t0 * DIM];

    float acc[4][8];
#pragma unroll
    for (int t = 0; t < 4; t++)
#pragma unroll
        for (int e = 0; e < 8; e++) acc[t][e] = 0.f;

    for (int d = lane; d < DIM; d += 32) {
        float4 ga = *(const float4*)(gw + (size_t)d * NEXP);
        float4 gb = *(const float4*)(gw + (size_t)d * NEXP + 4);
#pragma unroll
        for (int t = 0; t < 4; t++) {
            float xv = xb[t * DIM + d];
            xo[t * DIM + d] = __float2half(xv);
            acc[t][0] += xv * ga.x; acc[t][1] += xv * ga.y;
            acc[t][2] += xv * ga.z; acc[t][3] += xv * ga.w;
            acc[t][4] += xv * gb.x; acc[t][5] += xv * gb.y;
            acc[t][6] += xv * gb.z; acc[t][7] += xv * gb.w;
        }
    }
#pragma unroll
    for (int t = 0; t < 4; t++)
#pragma unroll
        for (int e = 0; e < 8; e++)
#pragma unroll
            for (int s = 16; s > 0; s >>= 1)
                acc[t][e] += __shfl_xor_sync(0xFFFFFFFFu, acc[t][e], s);

    if (lane < 4) {
        int t = t0 + lane;
        float* a = acc[lane];
        int e0 = 0; float b0 = a[0];
#pragma unroll
        for (int e = 1; e < NEXP; e++) if (a[e] > b0) { b0 = a[e]; e0 = e; }
        int e1 = -1; float b1 = -INFINITY;
#pragma unroll
        for (int e = 0; e < NEXP; e++) if (e != e0 && a[e] > b1) { b1 = a[e]; e1 = e; }
        float w0 = 1.f / (1.f + expf(b1 - b0));
        int ee[2] = { e0, e1 };
        float ww[2] = { w0, 1.f - w0 };
#pragma unroll
        for (int s = 0; s < 2; s++) {
            int pos = atomicAdd(&g_cursor[ee[s]], 1);
            int idx = ee[s] * CAP + pos;
            g_pair_token[idx]  = t;
            g_pair_weight[idx] = ww[s];
            g_tok2pair[2 * t + s] = idx;
        }
    }
}

// ======================= mma.sync GEMM cores =======================
#define PLANE_B (128 * 128)             // 16384
#define STAGE_B (2 * PLANE_B)           // 32768
#define SMEM_BYTES (2 * STAGE_B)        // 65536 -> 2 CTAs/SM

// Shared GEMM body (converged structure).
// G1: H = silu(X_gathered @ W1t^T), K=1024 (NC=16)
// !G1: O(fp16) = w * (H @ W2t^T),   K=4096 (NC=64)
template <int NC, bool G1>
__device__ __forceinline__ void gemm_body(int e, char* dynsmem) {
    const int cnt  = g_cursor[e];
    const int row0 = blockIdx.y * 128;
    if (row0 >= cnt) return;
    const int off  = e * CAP;
    const int n0   = blockIdx.x * 128;

    const uint32_t sb = smem_u32(dynsmem);
    const int tid  = threadIdx.x;
    const int lane = tid & 31;
    const int wid  = tid >> 5;
    const int wm   = wid & 1;
    const int wn   = wid >> 1;

    const int r    = tid >> 1;
    const int half = tid & 1;
    const int row  = row0 + r;
    const bool vA  = row < cnt;

    const char* srcA;
    const char* srcB;
    if (G1) {
        int tok = vA ? g_pair_token[off + row] : 0;
        srcA = (const char*)(&g_X[0] + (size_t)tok * DIM) + half * 64;
        srcB = (const char*)(&g_W1t[0] + ((size_t)e * DFF + n0 + r) * DIM) + half * 64;
    } else {
        size_t p = (size_t)(vA ? off + row : off);
        srcA = (const char*)(&g_H[0] + p * DFF) + half * 64;
        srcB = (const char*)(&g_W2t[0] + ((size_t)e * DIM + n0 + r) * DFF) + half * 64;
    }
    uint32_t dstO[4];
#pragma unroll
    for (int j = 0; j < 4; j++)
        dstO[j] = swz((uint32_t)(r * 128 + half * 64 + j * 16));

    const int mat  = lane >> 3;
    const int lrow = lane & 7;
    const uint32_t xmask = (uint32_t)(lrow << 4);
    const uint32_t aBase = (uint32_t)((wm * 64 + (mat & 1) * 8 + lrow) * 128 + (mat >> 1) * 16);
    const uint32_t bBase = (uint32_t)((wn * 32 + (mat >> 1) * 8 + lrow) * 128 + (mat & 1) * 16);

    float c[4][4][4];
#pragma unroll
    for (int i = 0; i < 4; i++)
#pragma unroll
        for (int j = 0; j < 4; j++)
#pragma unroll
            for (int q = 0; q < 4; q++) c[i][j][q] = 0.f;

    auto load_stage = [&](int cidx) {
        uint32_t st = sb + (uint32_t)(cidx & 1) * STAGE_B;
        size_t ko = (size_t)cidx * 128;
#pragma unroll
        for (int j = 0; j < 4; j++)
            cp16(st + dstO[j], srcA + ko + j * 16, vA);
#pragma unroll
        for (int j = 0; j < 4; j++)
            cp16(st + PLANE_B + dstO[j], srcB + ko + j * 16, true);
        CP_COMMIT();
    };

    load_stage(0);

    for (int cidx = 0; cidx < NC; cidx++) {
        CP_WAIT(0);
        __syncthreads();
        if (cidx + 1 < NC) load_stage(cidx + 1);

        uint32_t st = sb + (uint32_t)(cidx & 1) * STAGE_B;
#pragma unroll
        for (int ks = 0; ks < 4; ks++) {
            uint32_t kso = (uint32_t)(ks * 32);
            uint32_t a[4][4], b[2][4];
#pragma unroll
            for (int tm = 0; tm < 4; tm++)
                ldsm_x4(a[tm], st + ((aBase + (uint32_t)(tm * 16 * 128) + kso) ^ xmask));
#pragma unroll
            for (int tp = 0; tp < 2; tp++)
                ldsm_x4(b[tp], st + PLANE_B + ((bBase + (uint32_t)(tp * 16 * 128) + kso) ^ xmask));
#pragma unroll
            for (int tm = 0; tm < 4; tm++)
#pragma unroll
                for (int tp = 0; tp < 2; tp++) {
                    mma_fp16(c[tm][tp * 2 + 0], a[tm], b[tp][0], b[tp][1]);
                    mma_fp16(c[tm][tp * 2 + 1], a[tm], b[tp][2], b[tp][3]);
                }
        }
    }

    const int g   = lane >> 2;
    const int tig = lane & 3;
#pragma unroll
    for (int tm = 0; tm < 4; tm++) {
#pragma unroll
        for (int half_m = 0; half_m < 2; half_m++) {
            int rr = row0 + wm * 64 + tm * 16 + g + half_m * 8;
            if (rr >= cnt) continue;
            if (G1) {
                size_t hrow = (size_t)(off + rr) * DFF + n0 + wn * 32 + tig * 2;
#pragma unroll
                for (int tn = 0; tn < 4; tn++) {
                    float v0 = c[tm][tn][half_m * 2 + 0];
                    float v1 = c[tm][tn][half_m * 2 + 1];
                    v0 = v0 / (1.f + __expf(-v0));
                    v1 = v1 / (1.f + __expf(-v1));
                    *(__half2*)(&g_H[0] + hrow + tn * 8) = __floats2half2_rn(v0, v1);
                }
            } else {
                float wgt = g_pair_weight[off + rr];
                size_t orow = (size_t)(off + rr) * DIM + n0 + wn * 32 + tig * 2;
#pragma unroll
                for (int tn = 0; tn < 4; tn++) {
                    *(__half2*)(&g_O[0] + orow + tn * 8) =
                        __floats2half2_rn(wgt * c[tm][tn][half_m * 2 + 0],
                                          wgt * c[tm][tn][half_m * 2 + 1]);
                }
            }
        }
    }
}

// ======== kernel 2: GEMM1 (z in [0,8)) + convert W2 (z in [8,10)) ========
__global__ __launch_bounds__(256, 2) void k_gemm1_conv2(const float* __restrict__ w2) {
    extern __shared__ char dynsmem[];
    int z = blockIdx.z;
    if (z < NEXP) {
        gemm_body<DIM / 64, true>(z, dynsmem);
        return;
    }
    // convert W2: idx in [0, 8192); grid y=128 -> 4096 blocks per z-slice
    int idx = (z - NEXP) * 4096 + blockIdx.y * 32 + blockIdx.x;
    if (idx >= 8192) return;
    int e = idx >> 10, t = idx & 1023;
    int n0 = (t & 15) * 64, k0 = (t >> 4) * 64;
    float (*tile)[65] = (float(*)[65])dynsmem;
    conv_tile<DIM>(w2 + (size_t)e * DFF * DIM,
                   &g_W2t[(size_t)e * DIM * DFF], tile, n0, k0, DFF);
}

// ======== kernel 3: GEMM2 ========
__global__ __launch_bounds__(256, 2) void k_gemm2() {
    extern __shared__ char dynsmem[];
    gemm_body<DFF / 64, false>(blockIdx.z, dynsmem);
}

// ======== kernel 4: combine (fp16 O -> fp32 y) + cursor reset for next run ==
__global__ void k_combine(float* __restrict__ y) {
    if (blockIdx.x == 0 && threadIdx.x < NEXP)
        g_cursor[threadIdx.x] = 0;
    int i = blockIdx.x * blockDim.x + threadIdx.x;
    const int V = DIM / 4;
    if (i >= N_TOK * V) return;
    int tok = i / V;
    int c   = i - tok * V;
    int p0 = g_tok2pair[2 * tok];
    int p1 = g_tok2pair[2 * tok + 1];
    const __half2* o0 = (const __half2*)(&g_O[0] + (size_t)p0 * DIM) + c * 2;
    const __half2* o1 = (const __half2*)(&g_O[0] + (size_t)p1 * DIM) + c * 2;
    float2 a0 = __half22float2(o0[0]);
    float2 a1 = __half22float2(o0[1]);
    float2 b0 = __half22float2(o1[0]);
    float2 b1 = __half22float2(o1[1]);
    float4 r;
    r.x = a0.x + b0.x; r.y = a0.y + b0.y;
    r.z = a1.x + b1.x; r.w = a1.y + b1.y;
    ((float4*)y)[i] = r;
}

// ======================= launch =======================
extern "C" void kernel_launch(void* const* d_in, const int* in_sizes, int n_in,
                              void* d_out, int out_size) {
    const float* x  = (const float*)d_in[0];   // [N, D]
    const float* gw = (const float*)d_in[1];   // [D, E]
    const float* w1 = (const float*)d_in[2];   // [E, D, DFF]
    const float* w2 = (const float*)d_in[3];   // [E, DFF, D]
    float* y = (float*)d_out;

    cudaFuncSetAttribute((const void*)k_gemm1_conv2,
                         cudaFuncAttributeMaxDynamicSharedMemorySize, SMEM_BYTES);
    cudaFuncSetAttribute((const void*)k_gemm2,
                         cudaFuncAttributeMaxDynamicSharedMemorySize, SMEM_BYTES);

    // #1: convert W1 + router (direct slab assignment; cursors zeroed by
    //     previous run's combine / zero-init statics on first run)
    k_conv1_router<<<8192 + 256, 256>>>(w1, x, gw);
    // #2: GEMM1 + convert W2 on z-slices [8,10)
    k_gemm1_conv2<<<dim3(DFF / 128, 128, NEXP + 2), 256, SMEM_BYTES>>>(w2);
    // #3: GEMM2 (y=64 suffices: cnt <= CAP = 8192)
    k_gemm2<<<dim3(DIM / 128, CAP / 128, NEXP), 256, SMEM_BYTES>>>();
    // #4: combine (+ cursor reset for next graph replay)
    k_combine<<<(N_TOK * DIM / 4 + 255) / 256, 256>>>(y);
}